// round 12
// baseline (speedup 1.0000x reference)
#include <cuda_runtime.h>
#include <cuda_fp16.h>
#include <cstdint>

#define D       128
#define KTOT    640
#define MAXG    10112        // padded segment capacity (multiple of 128)
#define WTILES  80           // 20 k-tiles x 4 n-tiles of 32x32 for W split

// Scratch (device globals; zero-initialized; feats rows >= G stay 0 forever)
__device__ int g_segoff[MAXG + 1];
__device__ __align__(16) __half g_fh[(size_t)MAXG * KTOT];   // feats fp16
// W TRANSPOSED [n=128][k=640], fp16 hi/lo split
__device__ __align__(16) __half g_wh[128 * KTOT];
__device__ __align__(16) __half g_wl[128 * KTOT];

// ---------------------------------------------------------------------------
// Kernel 1 (scan): boundary scan over sorted batch -> segment offsets.
// 8 ids per thread; int64/int32 detected via words[N-1] (int64 -> 0).
// ---------------------------------------------------------------------------
__global__ __launch_bounds__(256) void scan_kernel(const int* __restrict__ words,
                                                   int N, int G)
{
    const bool is64 = (words[N - 1] == 0);
    int i0 = (blockIdx.x * 256 + threadIdx.x) * 8;
    if (i0 >= N) return;

    if (i0 + 9 <= N) {
        int v[9];
        if (is64) {
            #pragma unroll
            for (int j = 0; j < 4; ++j) {
                int4 w = *(const int4*)(words + 2 * i0 + 4 * j);
                v[2 * j] = w.x; v[2 * j + 1] = w.z;
            }
            v[8] = words[2 * (i0 + 8)];
        } else {
            int4 w0 = *(const int4*)(words + i0);
            int4 w1 = *(const int4*)(words + i0 + 4);
            v[0] = w0.x; v[1] = w0.y; v[2] = w0.z; v[3] = w0.w;
            v[4] = w1.x; v[5] = w1.y; v[6] = w1.z; v[7] = w1.w;
            v[8] = words[i0 + 8];
        }
        if (i0 == 0)
            for (int g = 0; g <= v[0]; ++g) g_segoff[g] = 0;
        #pragma unroll
        for (int j = 0; j < 8; ++j)
            for (int g = v[j] + 1; g <= v[j + 1]; ++g) g_segoff[g] = i0 + j + 1;
    } else {
        for (int i = i0; i < N && i < i0 + 8; ++i) {
            int bi = is64 ? words[2 * i] : words[i];
            if (i == 0)
                for (int g = 0; g <= bi; ++g) g_segoff[g] = 0;
            if (i == N - 1) {
                for (int g = bi + 1; g <= G; ++g) g_segoff[g] = N;
            } else {
                int bn = is64 ? words[2 * (i + 1)] : words[i + 1];
                for (int g = bi + 1; g <= bn; ++g) g_segoff[g] = i + 1;
            }
        }
    }
}

// ---------------------------------------------------------------------------
// Kernel 2 (fused): blocks [0,G): per-segment reduction (streams 256MB);
// blocks [G,G+WTILES): W split+transpose (hidden under the reduce).
// Packed arithmetic: sum/sumsq via f32x2, min/max via f16x2 (exact).
// feats row: [sum/sqrt(50) | mean | min | max | std] (5 x 128), fp16.
// ---------------------------------------------------------------------------
#define ACCP(v)                                                                \
    do {                                                                       \
        uint64_t p01, p23; unsigned h01u, h23u;                                \
        asm("mov.b64 %0,{%1,%2};" : "=l"(p01) : "f"((v).x), "f"((v).y));       \
        asm("mov.b64 %0,{%1,%2};" : "=l"(p23) : "f"((v).z), "f"((v).w));       \
        asm("add.rn.f32x2 %0,%0,%1;" : "+l"(sum01) : "l"(p01));                \
        asm("add.rn.f32x2 %0,%0,%1;" : "+l"(sum23) : "l"(p23));                \
        asm("fma.rn.f32x2 %0,%1,%1,%0;" : "+l"(sq01) : "l"(p01));              \
        asm("fma.rn.f32x2 %0,%1,%1,%0;" : "+l"(sq23) : "l"(p23));              \
        asm("cvt.rn.f16x2.f32 %0,%1,%2;" : "=r"(h01u) : "f"((v).y), "f"((v).x)); \
        asm("cvt.rn.f16x2.f32 %0,%1,%2;" : "=r"(h23u) : "f"((v).w), "f"((v).z)); \
        __half2 hh01 = *reinterpret_cast<__half2*>(&h01u);                     \
        __half2 hh23 = *reinterpret_cast<__half2*>(&h23u);                     \
        mn01 = __hmin2(mn01, hh01); mx01 = __hmax2(mx01, hh01);                \
        mn23 = __hmin2(mn23, hh23); mx23 = __hmax2(mx23, hh23);                \
    } while (0)

__global__ __launch_bounds__(128) void seg_reduce_kernel(const float* __restrict__ x,
                                                         const float* __restrict__ W,
                                                         int G)
{
    int t = threadIdx.x;
    int gb = blockIdx.x;

    if (gb >= G) {
        // ---- W split + transpose: 32x32 tile, both sides coalesced ----
        __shared__ float s[32][33];
        int tb = gb - G;
        int k0 = (tb % 20) * 32;
        int n0 = (tb / 20) * 32;
        int tx = t & 31;
        int ty = t >> 5;                   // 0..3
        #pragma unroll
        for (int it = 0; it < 8; ++it) {
            int r = ty + it * 4;
            s[r][tx] = W[(size_t)(k0 + r) * 128 + n0 + tx];
        }
        __syncthreads();
        #pragma unroll
        for (int it = 0; it < 8; ++it) {
            int n = ty + it * 4;
            float v = s[tx][n];
            __half h = __float2half_rn(v);
            size_t o = (size_t)(n0 + n) * KTOT + k0 + tx;
            g_wh[o] = h;
            g_wl[o] = __float2half_rn(v - __half2float(h));
        }
        return;
    }

    int g = gb;
    int rg   = t >> 5;
    int lane = t & 31;
    int c4   = lane * 4;

    int s0v = g_segoff[g];
    int e0v = g_segoff[g + 1];
    int cnt = e0v - s0v;

    uint64_t sum01 = 0ULL, sum23 = 0ULL, sq01 = 0ULL, sq23 = 0ULL;
    const __half2 hpos = __halves2half2(__ushort_as_half(0x7C00), __ushort_as_half(0x7C00));
    const __half2 hneg = __halves2half2(__ushort_as_half(0xFC00), __ushort_as_half(0xFC00));
    __half2 mn01 = hpos, mn23 = hpos, mx01 = hneg, mx23 = hneg;

    const float* base = x + (size_t)s0v * D + c4;
    int r = rg;
    for (; r + 12 < cnt; r += 16) {        // 4 float4 in flight
        float4 v0 = __ldcs((const float4*)(base + (size_t)r * D));
        float4 v1 = __ldcs((const float4*)(base + (size_t)(r + 4) * D));
        float4 v2 = __ldcs((const float4*)(base + (size_t)(r + 8) * D));
        float4 v3 = __ldcs((const float4*)(base + (size_t)(r + 12) * D));
        ACCP(v0); ACCP(v1); ACCP(v2); ACCP(v3);
    }
    for (; r + 4 < cnt; r += 8) {
        float4 v0 = __ldcs((const float4*)(base + (size_t)r * D));
        float4 v1 = __ldcs((const float4*)(base + (size_t)(r + 4) * D));
        ACCP(v0); ACCP(v1);
    }
    for (; r < cnt; r += 4) {
        float4 v0 = __ldcs((const float4*)(base + (size_t)r * D));
        ACCP(v0);
    }

    float s0, s1, s2, s3, q0, q1, q2, q3;
    asm("mov.b64 {%0,%1},%2;" : "=f"(s0), "=f"(s1) : "l"(sum01));
    asm("mov.b64 {%0,%1},%2;" : "=f"(s2), "=f"(s3) : "l"(sum23));
    asm("mov.b64 {%0,%1},%2;" : "=f"(q0), "=f"(q1) : "l"(sq01));
    asm("mov.b64 {%0,%1},%2;" : "=f"(q2), "=f"(q3) : "l"(sq23));
    float m0 = __low2float(mn01), m1 = __high2float(mn01);
    float m2 = __low2float(mn23), m3 = __high2float(mn23);
    float M0 = __low2float(mx01), M1 = __high2float(mx01);
    float M2 = __low2float(mx23), M3 = __high2float(mx23);

    __shared__ float s_sum[512], s_sq[512], s_mn[512], s_mx[512];
    int sb = rg * 128 + c4;
    s_sum[sb] = s0; s_sum[sb+1] = s1; s_sum[sb+2] = s2; s_sum[sb+3] = s3;
    s_sq [sb] = q0; s_sq [sb+1] = q1; s_sq [sb+2] = q2; s_sq [sb+3] = q3;
    s_mn [sb] = m0; s_mn [sb+1] = m1; s_mn [sb+2] = m2; s_mn [sb+3] = m3;
    s_mx [sb] = M0; s_mx [sb+1] = M1; s_mx [sb+2] = M2; s_mx [sb+3] = M3;
    __syncthreads();

    float sum = s_sum[t] + s_sum[t+128] + s_sum[t+256] + s_sum[t+384];
    float sq  = s_sq [t] + s_sq [t+128] + s_sq [t+256] + s_sq [t+384];
    float mn  = fminf(fminf(s_mn[t], s_mn[t+128]), fminf(s_mn[t+256], s_mn[t+384]));
    float mx  = fmaxf(fmaxf(s_mx[t], s_mx[t+128]), fmaxf(s_mx[t+256], s_mx[t+384]));

    float fc   = fmaxf((float)cnt, 1.0f);
    float mean = sum / fc;
    float stdv = sqrtf(fmaxf(sq / fc - mean * mean, 1e-9f));
    if (cnt == 0) { mn = 0.f; mx = 0.f; }

    size_t fb = (size_t)g * KTOT + t;
    g_fh[fb + 0 * D] = __float2half_rn(sum * 0.14142135623730951f);  // 1/sqrt(50)
    g_fh[fb + 1 * D] = __float2half_rn(mean);
    g_fh[fb + 2 * D] = __float2half_rn(mn);
    g_fh[fb + 3 * D] = __float2half_rn(mx);
    g_fh[fb + 4 * D] = __float2half_rn(stdv);
}

// ---------------------------------------------------------------------------
// Kernel 3: GEMM out = feats[G,640] @ W + bias.
// fp16 2-pass (A*Bhi + A*Blo). BM=128, BN=64, BK=64; 512 threads = 16 warps
// (4M x 4N), warp tile 32x16. cp.async double buffer; ldmatrix.x4 fragments.
// grid = ceil(G/128) * 2 = 158 blocks; 73.7KB smem -> 3 blocks/SM.
// ---------------------------------------------------------------------------
#define SSTR    72
#define A_BUF   (128 * SSTR)                // 9216 halfs
#define B_BUF   (64 * SSTR)                 // 4608 halfs
#define STAGE   (A_BUF + 2 * B_BUF)         // 18432 halfs
#define SMEM_ELEMS (2 * STAGE)              // 36864 halfs = 73728 B
#define NKT     (KTOT / 64)                 // 10

__device__ __forceinline__ void cp16(__half* dst, const __half* src)
{
    unsigned sa = (unsigned)__cvta_generic_to_shared(dst);
    asm volatile("cp.async.cg.shared.global [%0], [%1], 16;\n" :: "r"(sa), "l"(src));
}

#define LDSM4(r0, r1, r2, r3, addr)                                           \
    asm volatile("ldmatrix.sync.aligned.m8n8.x4.shared.b16 {%0,%1,%2,%3}, [%4];" \
        : "=r"(r0), "=r"(r1), "=r"(r2), "=r"(r3) : "r"(addr))

#define MMA_F16(acc, a0, a1, a2, a3, b0, b1)                                  \
    asm volatile(                                                             \
        "mma.sync.aligned.m16n8k16.row.col.f32.f16.f16.f32 "                  \
        "{%0,%1,%2,%3}, {%4,%5,%6,%7}, {%8,%9}, {%0,%1,%2,%3};\n"             \
        : "+f"((acc)[0]), "+f"((acc)[1]), "+f"((acc)[2]), "+f"((acc)[3])      \
        : "r"(a0), "r"(a1), "r"(a2), "r"(a3), "r"(b0), "r"(b1))

__global__ __launch_bounds__(512, 3) void gemm_kernel(const float* __restrict__ bias,
                                                      float* __restrict__ out, int G)
{
    extern __shared__ __half sm[];
    int tid  = threadIdx.x;
    int warp = tid >> 5;
    int lane = tid & 31;
    int wm   = warp >> 2;              // 0..3  (M: rows wm*32)
    int wn   = warp & 3;               // 0..3  (N: cols wn*16)
    int bm   = (blockIdx.x >> 1) * 128;
    int bn   = (blockIdx.x & 1) * 64;

    float acc[2][2][4];
    #pragma unroll
    for (int mt = 0; mt < 2; ++mt)
        #pragma unroll
        for (int nt = 0; nt < 2; ++nt)
            #pragma unroll
            for (int r2 = 0; r2 < 4; ++r2) acc[mt][nt][r2] = 0.f;

    unsigned smbase = (unsigned)__cvta_generic_to_shared(sm);
    int mat = lane >> 3, rr = lane & 7;
    unsigned offA0 = ((wm * 32 +      (mat & 1) * 8 + rr) * SSTR + (mat >> 1) * 8) * 2;
    unsigned offA1 = ((wm * 32 + 16 + (mat & 1) * 8 + rr) * SSTR + (mat >> 1) * 8) * 2;
    unsigned offB  = ((unsigned)A_BUF + (wn * 16 + (mat >> 1) * 8 + rr) * SSTR
                      + (mat & 1) * 8) * 2;

    // 2048 x 16B cp.async per stage, 4 per thread
    auto load_stage = [&](int s, int kt) {
        int kb = kt * 64;
        #pragma unroll
        for (int i = 0; i < 4; ++i) {
            int c = tid + i * 512;
            if (c < 1024) {                    // A: 128 rows x 8 chunks
                int row = c >> 3;
                int cw  = c & 7;
                cp16(sm + s * STAGE + row * SSTR + cw * 8,
                     g_fh + (size_t)(bm + row) * KTOT + kb + cw * 8);
            } else {                           // B hi/lo: 64 rows x 8 chunks each
                int c2  = c - 1024;
                int hl  = c2 >> 9;
                int c3  = c2 & 511;
                int row = c3 >> 3;
                int cw  = c3 & 7;
                const __half* src = (hl ? g_wl : g_wh)
                                    + (size_t)(bn + row) * KTOT + kb + cw * 8;
                cp16(sm + s * STAGE + A_BUF + hl * B_BUF + row * SSTR + cw * 8, src);
            }
        }
    };

    load_stage(0, 0);
    asm volatile("cp.async.commit_group;\n");

    for (int kt = 0; kt < NKT; ++kt) {
        int s = kt & 1;
        if (kt + 1 < NKT) {
            load_stage(s ^ 1, kt + 1);
            asm volatile("cp.async.commit_group;\n");
            asm volatile("cp.async.wait_group 1;\n");
        } else {
            asm volatile("cp.async.wait_group 0;\n");
        }
        __syncthreads();

        unsigned sOff = smbase + (unsigned)(s * STAGE) * 2;

        #pragma unroll
        for (int ks = 0; ks < 4; ++ks) {
            unsigned kOff = (unsigned)(ks * 16) * 2;
            unsigned a0[4], a1[4], bh[4], bl[4];
            LDSM4(a0[0], a0[1], a0[2], a0[3], sOff + offA0 + kOff);
            LDSM4(a1[0], a1[1], a1[2], a1[3], sOff + offA1 + kOff);
            LDSM4(bh[0], bh[1], bh[2], bh[3], sOff + offB + kOff);
            LDSM4(bl[0], bl[1], bl[2], bl[3], sOff + offB + (unsigned)(B_BUF * 2) + kOff);

            MMA_F16(acc[0][0], a0[0], a0[1], a0[2], a0[3], bh[0], bh[1]);
            MMA_F16(acc[0][1], a0[0], a0[1], a0[2], a0[3], bh[2], bh[3]);
            MMA_F16(acc[1][0], a1[0], a1[1], a1[2], a1[3], bh[0], bh[1]);
            MMA_F16(acc[1][1], a1[0], a1[1], a1[2], a1[3], bh[2], bh[3]);
            MMA_F16(acc[0][0], a0[0], a0[1], a0[2], a0[3], bl[0], bl[1]);
            MMA_F16(acc[0][1], a0[0], a0[1], a0[2], a0[3], bl[2], bl[3]);
            MMA_F16(acc[1][0], a1[0], a1[1], a1[2], a1[3], bl[0], bl[1]);
            MMA_F16(acc[1][1], a1[0], a1[1], a1[2], a1[3], bl[2], bl[3]);
        }
        __syncthreads();
    }

    // Epilogue: direct fp32 store + bias
    #pragma unroll
    for (int mt = 0; mt < 2; ++mt) {
        #pragma unroll
        for (int nt = 0; nt < 2; ++nt) {
            int row = bm + wm * 32 + mt * 16 + (lane >> 2);
            int n   = bn + wn * 16 + nt * 8 + (lane & 3) * 2;
            float b0 = bias[n];
            float b1 = bias[n + 1];
            if (row < G) {
                float2 v = { acc[mt][nt][0] + b0, acc[mt][nt][1] + b1 };
                *(float2*)(out + (size_t)row * 128 + n) = v;
            }
            if (row + 8 < G) {
                float2 v = { acc[mt][nt][2] + b0, acc[mt][nt][3] + b1 };
                *(float2*)(out + (size_t)(row + 8) * 128 + n) = v;
            }
        }
    }
}

// ---------------------------------------------------------------------------
// Launch. Inputs: x[f32 N*128], batch[int64/int32 N], W[f32 640*128],
// b[f32 128], num_segments (ignored; G = out_size/128).
// ---------------------------------------------------------------------------
extern "C" void kernel_launch(void* const* d_in, const int* in_sizes, int n_in,
                              void* d_out, int out_size)
{
    const float* x     = (const float*)d_in[0];
    const int*   batch = (const int*)d_in[1];
    const float* W     = (const float*)d_in[2];
    const float* bias  = (const float*)d_in[3];
    float*       out   = (float*)d_out;

    int N = in_sizes[0] / D;
    int G = out_size / 128;
    int NB = (N + 2047) / 2048;

    static bool attr_done = false;
    if (!attr_done) {
        cudaFuncSetAttribute(gemm_kernel,
                             cudaFuncAttributeMaxDynamicSharedMemorySize,
                             SMEM_ELEMS * (int)sizeof(__half));
        attr_done = true;
    }

    scan_kernel<<<NB, 256>>>(batch, N, G);
    seg_reduce_kernel<<<G + WTILES, 128>>>(x, W, G);
    gemm_kernel<<<((G + 127) / 128) * 2, 512, SMEM_ELEMS * sizeof(__half)>>>(bias, out, G);
}

// round 13
// speedup vs baseline: 1.0407x; 1.0407x over previous
#include <cuda_runtime.h>
#include <cuda_fp16.h>
#include <cstdint>

#define D       128
#define KTOT    640
#define MAXG    10048        // padded segment capacity (multiple of 64)
#define WTILES  80           // 20 k-tiles x 4 n-tiles of 32x32 for W split

// Scratch (device globals; zero-initialized; feats rows >= G stay 0 forever)
__device__ int g_segoff[MAXG + 1];
__device__ int g_cnt[512];                                   // split-K tile counters
__device__ __align__(16) __half g_fh[(size_t)MAXG * KTOT];   // feats fp16
// W TRANSPOSED [n=128][k=640], fp16 hi/lo split
__device__ __align__(16) __half g_wh[128 * KTOT];
__device__ __align__(16) __half g_wl[128 * KTOT];
// per-block 64x64 fp32 partials (628 blocks max -> pad to 640)
__device__ __align__(16) float g_part[(size_t)640 * 4096];

// ---------------------------------------------------------------------------
// Kernel 1 (scan): boundary scan over sorted batch -> segment offsets.
// Also re-zeroes the split-K counters every launch (block 0).
// 8 ids per thread; int64/int32 detected via words[N-1] (int64 -> 0).
// ---------------------------------------------------------------------------
__global__ __launch_bounds__(256) void scan_kernel(const int* __restrict__ words,
                                                   int N, int G)
{
    int t = threadIdx.x;
    if (blockIdx.x == 0) {               // reset split-K counters for this run
        g_cnt[t] = 0;
        g_cnt[t + 256] = 0;
    }

    const bool is64 = (words[N - 1] == 0);
    int i0 = (blockIdx.x * 256 + t) * 8;
    if (i0 >= N) return;

    if (i0 + 9 <= N) {
        int v[9];
        if (is64) {
            #pragma unroll
            for (int j = 0; j < 4; ++j) {
                int4 w = *(const int4*)(words + 2 * i0 + 4 * j);
                v[2 * j] = w.x; v[2 * j + 1] = w.z;
            }
            v[8] = words[2 * (i0 + 8)];
        } else {
            int4 w0 = *(const int4*)(words + i0);
            int4 w1 = *(const int4*)(words + i0 + 4);
            v[0] = w0.x; v[1] = w0.y; v[2] = w0.z; v[3] = w0.w;
            v[4] = w1.x; v[5] = w1.y; v[6] = w1.z; v[7] = w1.w;
            v[8] = words[i0 + 8];
        }
        if (i0 == 0)
            for (int g = 0; g <= v[0]; ++g) g_segoff[g] = 0;
        #pragma unroll
        for (int j = 0; j < 8; ++j)
            for (int g = v[j] + 1; g <= v[j + 1]; ++g) g_segoff[g] = i0 + j + 1;
    } else {
        for (int i = i0; i < N && i < i0 + 8; ++i) {
            int bi = is64 ? words[2 * i] : words[i];
            if (i == 0)
                for (int g = 0; g <= bi; ++g) g_segoff[g] = 0;
            if (i == N - 1) {
                for (int g = bi + 1; g <= G; ++g) g_segoff[g] = N;
            } else {
                int bn = is64 ? words[2 * (i + 1)] : words[i + 1];
                for (int g = bi + 1; g <= bn; ++g) g_segoff[g] = i + 1;
            }
        }
    }
}

// ---------------------------------------------------------------------------
// Kernel 2 (fused): blocks [0,G): per-segment reduction (streams 256MB);
// blocks [G,G+WTILES): W split+transpose (hidden under the reduce).
// Packed arithmetic: sum/sumsq via f32x2, min/max via f16x2 (exact).
// feats row: [sum/sqrt(50) | mean | min | max | std] (5 x 128), fp16.
// ---------------------------------------------------------------------------
#define ACCP(v)                                                                \
    do {                                                                       \
        uint64_t p01, p23; unsigned h01u, h23u;                                \
        asm("mov.b64 %0,{%1,%2};" : "=l"(p01) : "f"((v).x), "f"((v).y));       \
        asm("mov.b64 %0,{%1,%2};" : "=l"(p23) : "f"((v).z), "f"((v).w));       \
        asm("add.rn.f32x2 %0,%0,%1;" : "+l"(sum01) : "l"(p01));                \
        asm("add.rn.f32x2 %0,%0,%1;" : "+l"(sum23) : "l"(p23));                \
        asm("fma.rn.f32x2 %0,%1,%1,%0;" : "+l"(sq01) : "l"(p01));              \
        asm("fma.rn.f32x2 %0,%1,%1,%0;" : "+l"(sq23) : "l"(p23));              \
        asm("cvt.rn.f16x2.f32 %0,%1,%2;" : "=r"(h01u) : "f"((v).y), "f"((v).x)); \
        asm("cvt.rn.f16x2.f32 %0,%1,%2;" : "=r"(h23u) : "f"((v).w), "f"((v).z)); \
        __half2 hh01 = *reinterpret_cast<__half2*>(&h01u);                     \
        __half2 hh23 = *reinterpret_cast<__half2*>(&h23u);                     \
        mn01 = __hmin2(mn01, hh01); mx01 = __hmax2(mx01, hh01);                \
        mn23 = __hmin2(mn23, hh23); mx23 = __hmax2(mx23, hh23);                \
    } while (0)

__global__ __launch_bounds__(128) void seg_reduce_kernel(const float* __restrict__ x,
                                                         const float* __restrict__ W,
                                                         int G)
{
    int t = threadIdx.x;
    int gb = blockIdx.x;

    if (gb >= G) {
        // ---- W split + transpose: 32x32 tile, both sides coalesced ----
        __shared__ float s[32][33];
        int tb = gb - G;
        int k0 = (tb % 20) * 32;
        int n0 = (tb / 20) * 32;
        int tx = t & 31;
        int ty = t >> 5;                   // 0..3
        #pragma unroll
        for (int it = 0; it < 8; ++it) {
            int r = ty + it * 4;
            s[r][tx] = W[(size_t)(k0 + r) * 128 + n0 + tx];
        }
        __syncthreads();
        #pragma unroll
        for (int it = 0; it < 8; ++it) {
            int n = ty + it * 4;
            float v = s[tx][n];
            __half h = __float2half_rn(v);
            size_t o = (size_t)(n0 + n) * KTOT + k0 + tx;
            g_wh[o] = h;
            g_wl[o] = __float2half_rn(v - __half2float(h));
        }
        return;
    }

    int g = gb;
    int rg   = t >> 5;
    int lane = t & 31;
    int c4   = lane * 4;

    int s0v = g_segoff[g];
    int e0v = g_segoff[g + 1];
    int cnt = e0v - s0v;

    uint64_t sum01 = 0ULL, sum23 = 0ULL, sq01 = 0ULL, sq23 = 0ULL;
    const __half2 hpos = __halves2half2(__ushort_as_half(0x7C00), __ushort_as_half(0x7C00));
    const __half2 hneg = __halves2half2(__ushort_as_half(0xFC00), __ushort_as_half(0xFC00));
    __half2 mn01 = hpos, mn23 = hpos, mx01 = hneg, mx23 = hneg;

    const float* base = x + (size_t)s0v * D + c4;
    int r = rg;
    for (; r + 12 < cnt; r += 16) {        // 4 float4 in flight
        float4 v0 = __ldcs((const float4*)(base + (size_t)r * D));
        float4 v1 = __ldcs((const float4*)(base + (size_t)(r + 4) * D));
        float4 v2 = __ldcs((const float4*)(base + (size_t)(r + 8) * D));
        float4 v3 = __ldcs((const float4*)(base + (size_t)(r + 12) * D));
        ACCP(v0); ACCP(v1); ACCP(v2); ACCP(v3);
    }
    for (; r + 4 < cnt; r += 8) {
        float4 v0 = __ldcs((const float4*)(base + (size_t)r * D));
        float4 v1 = __ldcs((const float4*)(base + (size_t)(r + 4) * D));
        ACCP(v0); ACCP(v1);
    }
    for (; r < cnt; r += 4) {
        float4 v0 = __ldcs((const float4*)(base + (size_t)r * D));
        ACCP(v0);
    }

    float s0, s1, s2, s3, q0, q1, q2, q3;
    asm("mov.b64 {%0,%1},%2;" : "=f"(s0), "=f"(s1) : "l"(sum01));
    asm("mov.b64 {%0,%1},%2;" : "=f"(s2), "=f"(s3) : "l"(sum23));
    asm("mov.b64 {%0,%1},%2;" : "=f"(q0), "=f"(q1) : "l"(sq01));
    asm("mov.b64 {%0,%1},%2;" : "=f"(q2), "=f"(q3) : "l"(sq23));
    float m0 = __low2float(mn01), m1 = __high2float(mn01);
    float m2 = __low2float(mn23), m3 = __high2float(mn23);
    float M0 = __low2float(mx01), M1 = __high2float(mx01);
    float M2 = __low2float(mx23), M3 = __high2float(mx23);

    __shared__ float s_sum[512], s_sq[512], s_mn[512], s_mx[512];
    int sb = rg * 128 + c4;
    s_sum[sb] = s0; s_sum[sb+1] = s1; s_sum[sb+2] = s2; s_sum[sb+3] = s3;
    s_sq [sb] = q0; s_sq [sb+1] = q1; s_sq [sb+2] = q2; s_sq [sb+3] = q3;
    s_mn [sb] = m0; s_mn [sb+1] = m1; s_mn [sb+2] = m2; s_mn [sb+3] = m3;
    s_mx [sb] = M0; s_mx [sb+1] = M1; s_mx [sb+2] = M2; s_mx [sb+3] = M3;
    __syncthreads();

    float sum = s_sum[t] + s_sum[t+128] + s_sum[t+256] + s_sum[t+384];
    float sq  = s_sq [t] + s_sq [t+128] + s_sq [t+256] + s_sq [t+384];
    float mn  = fminf(fminf(s_mn[t], s_mn[t+128]), fminf(s_mn[t+256], s_mn[t+384]));
    float mx  = fmaxf(fmaxf(s_mx[t], s_mx[t+128]), fmaxf(s_mx[t+256], s_mx[t+384]));

    float fc   = fmaxf((float)cnt, 1.0f);
    float mean = sum / fc;
    float stdv = sqrtf(fmaxf(sq / fc - mean * mean, 1e-9f));
    if (cnt == 0) { mn = 0.f; mx = 0.f; }

    size_t fb = (size_t)g * KTOT + t;
    g_fh[fb + 0 * D] = __float2half_rn(sum * 0.14142135623730951f);  // 1/sqrt(50)
    g_fh[fb + 1 * D] = __float2half_rn(mean);
    g_fh[fb + 2 * D] = __float2half_rn(mn);
    g_fh[fb + 3 * D] = __float2half_rn(mx);
    g_fh[fb + 4 * D] = __float2half_rn(stdv);
}

// ---------------------------------------------------------------------------
// Kernel 3: GEMM out = feats[G,640] @ W + bias (split-K=2, last-block combine).
// fp16 2-pass (A*Bhi + A*Blo). BM=64, BN=64, BK=64; 256 threads; warp 32x16.
// cp.async double buffer; ldmatrix.x4 fragments. grid = (G/64)*2*2 = 628.
// Each block stores its 64x64 partial; the 2nd arriver per tile (counter)
// reads its partner's partial + own regs + bias and writes out directly.
// ---------------------------------------------------------------------------
#define SSTR    72
#define T_BUF   (64 * SSTR)                 // 4608 halfs
#define STAGE   (3 * T_BUF)                 // 13824 halfs
#define SMEM_ELEMS (2 * STAGE)              // 55296 B
#define NKT     (KTOT / 64)                 // 10
#define KHALF   (NKT / 2)                   // 5

__device__ __forceinline__ void cp16(__half* dst, const __half* src)
{
    unsigned sa = (unsigned)__cvta_generic_to_shared(dst);
    asm volatile("cp.async.cg.shared.global [%0], [%1], 16;\n" :: "r"(sa), "l"(src));
}

#define LDSM4(r0, r1, r2, r3, addr)                                           \
    asm volatile("ldmatrix.sync.aligned.m8n8.x4.shared.b16 {%0,%1,%2,%3}, [%4];" \
        : "=r"(r0), "=r"(r1), "=r"(r2), "=r"(r3) : "r"(addr))

#define MMA_F16(acc, a0, a1, a2, a3, b0, b1)                                  \
    asm volatile(                                                             \
        "mma.sync.aligned.m16n8k16.row.col.f32.f16.f16.f32 "                  \
        "{%0,%1,%2,%3}, {%4,%5,%6,%7}, {%8,%9}, {%0,%1,%2,%3};\n"             \
        : "+f"((acc)[0]), "+f"((acc)[1]), "+f"((acc)[2]), "+f"((acc)[3])      \
        : "r"(a0), "r"(a1), "r"(a2), "r"(a3), "r"(b0), "r"(b1))

__global__ __launch_bounds__(256, 3) void gemm_kernel(const float* __restrict__ bias,
                                                      float* __restrict__ out, int G)
{
    extern __shared__ __half sm[];
    int tid  = threadIdx.x;
    int warp = tid >> 5;
    int lane = tid & 31;
    int wm   = warp >> 2;
    int wn   = warp & 3;
    int bx   = blockIdx.x;
    int bm   = (bx >> 2) * 64;
    int bn   = ((bx >> 1) & 1) * 64;
    int kt0  = (bx & 1) * KHALF;

    float acc[2][2][4];
    #pragma unroll
    for (int mt = 0; mt < 2; ++mt)
        #pragma unroll
        for (int nt = 0; nt < 2; ++nt)
            #pragma unroll
            for (int r2 = 0; r2 < 4; ++r2) acc[mt][nt][r2] = 0.f;

    unsigned smbase = (unsigned)__cvta_generic_to_shared(sm);
    int mat = lane >> 3, rr = lane & 7;
    unsigned offA0 = ((wm * 32 +      (mat & 1) * 8 + rr) * SSTR + (mat >> 1) * 8) * 2;
    unsigned offA1 = ((wm * 32 + 16 + (mat & 1) * 8 + rr) * SSTR + (mat >> 1) * 8) * 2;
    unsigned offB  = ((unsigned)T_BUF + (wn * 16 + (mat >> 1) * 8 + rr) * SSTR
                      + (mat & 1) * 8) * 2;

    auto load_stage = [&](int s, int kt) {
        int kb = kt * 64;
        #pragma unroll
        for (int i = 0; i < 6; ++i) {
            int c   = tid + i * 256;
            int buf = c >> 9;                  // 0:A 1:Bhi 2:Blo
            int c2  = c & 511;
            int row = c2 >> 3;
            int cw  = c2 & 7;
            const __half* src;
            if (buf == 0)      src = g_fh + (size_t)(bm + row) * KTOT + kb + cw * 8;
            else if (buf == 1) src = g_wh + (size_t)(bn + row) * KTOT + kb + cw * 8;
            else               src = g_wl + (size_t)(bn + row) * KTOT + kb + cw * 8;
            cp16(sm + s * STAGE + buf * T_BUF + row * SSTR + cw * 8, src);
        }
    };

    load_stage(0, kt0);
    asm volatile("cp.async.commit_group;\n");

    for (int kt = kt0; kt < kt0 + KHALF; ++kt) {
        int s = (kt - kt0) & 1;
        if (kt + 1 < kt0 + KHALF) {
            load_stage(s ^ 1, kt + 1);
            asm volatile("cp.async.commit_group;\n");
            asm volatile("cp.async.wait_group 1;\n");
        } else {
            asm volatile("cp.async.wait_group 0;\n");
        }
        __syncthreads();

        unsigned sOff = smbase + (unsigned)(s * STAGE) * 2;

        #pragma unroll
        for (int ks = 0; ks < 4; ++ks) {
            unsigned kOff = (unsigned)(ks * 16) * 2;
            unsigned a0[4], a1[4], bh[4], bl[4];
            LDSM4(a0[0], a0[1], a0[2], a0[3], sOff + offA0 + kOff);
            LDSM4(a1[0], a1[1], a1[2], a1[3], sOff + offA1 + kOff);
            LDSM4(bh[0], bh[1], bh[2], bh[3], sOff + offB + kOff);
            LDSM4(bl[0], bl[1], bl[2], bl[3], sOff + offB + (unsigned)(T_BUF * 2) + kOff);

            MMA_F16(acc[0][0], a0[0], a0[1], a0[2], a0[3], bh[0], bh[1]);
            MMA_F16(acc[0][1], a0[0], a0[1], a0[2], a0[3], bh[2], bh[3]);
            MMA_F16(acc[1][0], a1[0], a1[1], a1[2], a1[3], bh[0], bh[1]);
            MMA_F16(acc[1][1], a1[0], a1[1], a1[2], a1[3], bh[2], bh[3]);
            MMA_F16(acc[0][0], a0[0], a0[1], a0[2], a0[3], bl[0], bl[1]);
            MMA_F16(acc[0][1], a0[0], a0[1], a0[2], a0[3], bl[2], bl[3]);
            MMA_F16(acc[1][0], a1[0], a1[1], a1[2], a1[3], bl[0], bl[1]);
            MMA_F16(acc[1][1], a1[0], a1[1], a1[2], a1[3], bl[2], bl[3]);
        }
        __syncthreads();
    }

    // ---- split-K epilogue: store partial, count, last block combines ----
    float* mypart = g_part + (size_t)bx * 4096;
    #pragma unroll
    for (int mt = 0; mt < 2; ++mt) {
        #pragma unroll
        for (int nt = 0; nt < 2; ++nt) {
            int lr = wm * 32 + mt * 16 + (lane >> 2);
            int ln = wn * 16 + nt * 8 + (lane & 3) * 2;
            float2 v0 = { acc[mt][nt][0], acc[mt][nt][1] };
            float2 v1 = { acc[mt][nt][2], acc[mt][nt][3] };
            *(float2*)(mypart + lr * 64 + ln) = v0;
            *(float2*)(mypart + (lr + 8) * 64 + ln) = v1;
        }
    }
    __threadfence();
    __syncthreads();
    __shared__ int s_last;
    if (tid == 0) s_last = atomicAdd(&g_cnt[bx >> 1], 1);
    __syncthreads();

    if (s_last == 1) {
        const float* op = g_part + (size_t)(bx ^ 1) * 4096;
        #pragma unroll
        for (int mt = 0; mt < 2; ++mt) {
            #pragma unroll
            for (int nt = 0; nt < 2; ++nt) {
                int lr = wm * 32 + mt * 16 + (lane >> 2);
                int ln = wn * 16 + nt * 8 + (lane & 3) * 2;
                int row = bm + lr;
                int n   = bn + ln;
                float2 p0 = __ldcg((const float2*)(op + lr * 64 + ln));
                float2 p1 = __ldcg((const float2*)(op + (lr + 8) * 64 + ln));
                float b0 = bias[n];
                float b1 = bias[n + 1];
                if (row < G) {
                    float2 v = { acc[mt][nt][0] + p0.x + b0,
                                 acc[mt][nt][1] + p0.y + b1 };
                    *(float2*)(out + (size_t)row * 128 + n) = v;
                }
                if (row + 8 < G) {
                    float2 v = { acc[mt][nt][2] + p1.x + b0,
                                 acc[mt][nt][3] + p1.y + b1 };
                    *(float2*)(out + (size_t)(row + 8) * 128 + n) = v;
                }
            }
        }
    }
}

// ---------------------------------------------------------------------------
// Launch. Inputs: x[f32 N*128], batch[int64/int32 N], W[f32 640*128],
// b[f32 128], num_segments (ignored; G = out_size/128).
// ---------------------------------------------------------------------------
extern "C" void kernel_launch(void* const* d_in, const int* in_sizes, int n_in,
                              void* d_out, int out_size)
{
    const float* x     = (const float*)d_in[0];
    const int*   batch = (const int*)d_in[1];
    const float* W     = (const float*)d_in[2];
    const float* bias  = (const float*)d_in[3];
    float*       out   = (float*)d_out;

    int N = in_sizes[0] / D;
    int G = out_size / 128;
    int NB = (N + 2047) / 2048;

    static bool attr_done = false;
    if (!attr_done) {
        cudaFuncSetAttribute(gemm_kernel,
                             cudaFuncAttributeMaxDynamicSharedMemorySize,
                             SMEM_ELEMS * (int)sizeof(__half));
        attr_done = true;
    }

    scan_kernel<<<NB, 256>>>(batch, N, G);
    seg_reduce_kernel<<<G + WTILES, 128>>>(x, W, G);
    gemm_kernel<<<((G + 63) / 64) * 4, 256, SMEM_ELEMS * sizeof(__half)>>>(bias, out, G);
}

// round 14
// speedup vs baseline: 1.1011x; 1.0581x over previous
#include <cuda_runtime.h>
#include <cuda_fp16.h>
#include <cstdint>

#define D       128
#define KTOT    640
#define MAXG    10048        // padded segment capacity (multiple of 64)
#define WTILES  80           // 20 k-tiles x 4 n-tiles of 32x32 for W split

// Scratch (device globals; zero-initialized; feats rows >= G stay 0 forever)
__device__ int g_segoff[MAXG + 1];
__device__ __align__(16) __half g_fh[(size_t)MAXG * KTOT];   // feats fp16
// W TRANSPOSED [n=128][k=640], fp16 hi/lo split
__device__ __align__(16) __half g_wh[128 * KTOT];
__device__ __align__(16) __half g_wl[128 * KTOT];

// ---------------------------------------------------------------------------
// Kernel 1 (scan + bias-init fused launch):
//  blocks [0,NB): boundary scan over sorted batch -> segment offsets.
//    2 ids per thread (980 blocks -> enough warps to hide DRAM latency).
//  blocks [NB,...): initialize out with bias (gemm accumulates atomically).
// int64/int32 detected via words[N-1] (int64 -> high word of last id is 0).
// ---------------------------------------------------------------------------
__global__ __launch_bounds__(256) void scan_kernel(const int* __restrict__ words,
                                                   const float* __restrict__ bias,
                                                   float* __restrict__ out,
                                                   int N, int G, int NB, int total4)
{
    int b = blockIdx.x;
    int t = threadIdx.x;

    if (b >= NB) {
        // ---- bias init: one float4 per thread ----
        int j = (b - NB) * 256 + t;
        if (j < total4) {
            int n = (j * 4) & 127;
            float4 v = { __ldg(bias + n), __ldg(bias + n + 1),
                         __ldg(bias + n + 2), __ldg(bias + n + 3) };
            *(float4*)(out + (size_t)j * 4) = v;
        }
        return;
    }

    const bool is64 = (words[N - 1] == 0);
    int i0 = (b * 256 + t) * 2;
    if (i0 >= N) return;

    if (i0 + 3 <= N) {
        int v0, v1, v2;
        if (is64) {
            int4 w = *(const int4*)(words + 2 * i0);
            v0 = w.x; v1 = w.z;
            v2 = words[2 * (i0 + 2)];
        } else {
            int2 w = *(const int2*)(words + i0);
            v0 = w.x; v1 = w.y;
            v2 = words[i0 + 2];
        }
        if (i0 == 0)
            for (int g = 0; g <= v0; ++g) g_segoff[g] = 0;
        for (int g = v0 + 1; g <= v1; ++g) g_segoff[g] = i0 + 1;
        for (int g = v1 + 1; g <= v2; ++g) g_segoff[g] = i0 + 2;
    } else {
        for (int i = i0; i < N && i < i0 + 2; ++i) {
            int bi = is64 ? words[2 * i] : words[i];
            if (i == 0)
                for (int g = 0; g <= bi; ++g) g_segoff[g] = 0;
            if (i == N - 1) {
                for (int g = bi + 1; g <= G; ++g) g_segoff[g] = N;
            } else {
                int bn = is64 ? words[2 * (i + 1)] : words[i + 1];
                for (int g = bi + 1; g <= bn; ++g) g_segoff[g] = i + 1;
            }
        }
    }
}

// ---------------------------------------------------------------------------
// Kernel 2 (fused): blocks [0,G): per-segment reduction (streams 256MB);
// blocks [G,G+WTILES): W split+transpose (hidden under the reduce).
// Packed arithmetic: sum/sumsq via f32x2, min/max via f16x2 (exact).
// feats row: [sum/sqrt(50) | mean | min | max | std] (5 x 128), fp16.
// ---------------------------------------------------------------------------
#define ACCP(v)                                                                \
    do {                                                                       \
        uint64_t p01, p23; unsigned h01u, h23u;                                \
        asm("mov.b64 %0,{%1,%2};" : "=l"(p01) : "f"((v).x), "f"((v).y));       \
        asm("mov.b64 %0,{%1,%2};" : "=l"(p23) : "f"((v).z), "f"((v).w));       \
        asm("add.rn.f32x2 %0,%0,%1;" : "+l"(sum01) : "l"(p01));                \
        asm("add.rn.f32x2 %0,%0,%1;" : "+l"(sum23) : "l"(p23));                \
        asm("fma.rn.f32x2 %0,%1,%1,%0;" : "+l"(sq01) : "l"(p01));              \
        asm("fma.rn.f32x2 %0,%1,%1,%0;" : "+l"(sq23) : "l"(p23));              \
        asm("cvt.rn.f16x2.f32 %0,%1,%2;" : "=r"(h01u) : "f"((v).y), "f"((v).x)); \
        asm("cvt.rn.f16x2.f32 %0,%1,%2;" : "=r"(h23u) : "f"((v).w), "f"((v).z)); \
        __half2 hh01 = *reinterpret_cast<__half2*>(&h01u);                     \
        __half2 hh23 = *reinterpret_cast<__half2*>(&h23u);                     \
        mn01 = __hmin2(mn01, hh01); mx01 = __hmax2(mx01, hh01);                \
        mn23 = __hmin2(mn23, hh23); mx23 = __hmax2(mx23, hh23);                \
    } while (0)

__global__ __launch_bounds__(128) void seg_reduce_kernel(const float* __restrict__ x,
                                                         const float* __restrict__ W,
                                                         int G)
{
    int t = threadIdx.x;
    int gb = blockIdx.x;

    if (gb >= G) {
        // ---- W split + transpose: 32x32 tile, both sides coalesced ----
        __shared__ float s[32][33];
        int tb = gb - G;
        int k0 = (tb % 20) * 32;
        int n0 = (tb / 20) * 32;
        int tx = t & 31;
        int ty = t >> 5;                   // 0..3
        #pragma unroll
        for (int it = 0; it < 8; ++it) {
            int r = ty + it * 4;
            s[r][tx] = W[(size_t)(k0 + r) * 128 + n0 + tx];
        }
        __syncthreads();
        #pragma unroll
        for (int it = 0; it < 8; ++it) {
            int n = ty + it * 4;
            float v = s[tx][n];
            __half h = __float2half_rn(v);
            size_t o = (size_t)(n0 + n) * KTOT + k0 + tx;
            g_wh[o] = h;
            g_wl[o] = __float2half_rn(v - __half2float(h));
        }
        return;
    }

    int g = gb;
    int rg   = t >> 5;
    int lane = t & 31;
    int c4   = lane * 4;

    int s0v = g_segoff[g];
    int e0v = g_segoff[g + 1];
    int cnt = e0v - s0v;

    uint64_t sum01 = 0ULL, sum23 = 0ULL, sq01 = 0ULL, sq23 = 0ULL;
    const __half2 hpos = __halves2half2(__ushort_as_half(0x7C00), __ushort_as_half(0x7C00));
    const __half2 hneg = __halves2half2(__ushort_as_half(0xFC00), __ushort_as_half(0xFC00));
    __half2 mn01 = hpos, mn23 = hpos, mx01 = hneg, mx23 = hneg;

    const float* base = x + (size_t)s0v * D + c4;
    int r = rg;
    for (; r + 12 < cnt; r += 16) {        // 4 float4 in flight
        float4 v0 = __ldcs((const float4*)(base + (size_t)r * D));
        float4 v1 = __ldcs((const float4*)(base + (size_t)(r + 4) * D));
        float4 v2 = __ldcs((const float4*)(base + (size_t)(r + 8) * D));
        float4 v3 = __ldcs((const float4*)(base + (size_t)(r + 12) * D));
        ACCP(v0); ACCP(v1); ACCP(v2); ACCP(v3);
    }
    for (; r + 4 < cnt; r += 8) {
        float4 v0 = __ldcs((const float4*)(base + (size_t)r * D));
        float4 v1 = __ldcs((const float4*)(base + (size_t)(r + 4) * D));
        ACCP(v0); ACCP(v1);
    }
    for (; r < cnt; r += 4) {
        float4 v0 = __ldcs((const float4*)(base + (size_t)r * D));
        ACCP(v0);
    }

    float s0, s1, s2, s3, q0, q1, q2, q3;
    asm("mov.b64 {%0,%1},%2;" : "=f"(s0), "=f"(s1) : "l"(sum01));
    asm("mov.b64 {%0,%1},%2;" : "=f"(s2), "=f"(s3) : "l"(sum23));
    asm("mov.b64 {%0,%1},%2;" : "=f"(q0), "=f"(q1) : "l"(sq01));
    asm("mov.b64 {%0,%1},%2;" : "=f"(q2), "=f"(q3) : "l"(sq23));
    float m0 = __low2float(mn01), m1 = __high2float(mn01);
    float m2 = __low2float(mn23), m3 = __high2float(mn23);
    float M0 = __low2float(mx01), M1 = __high2float(mx01);
    float M2 = __low2float(mx23), M3 = __high2float(mx23);

    __shared__ float s_sum[512], s_sq[512], s_mn[512], s_mx[512];
    int sb = rg * 128 + c4;
    s_sum[sb] = s0; s_sum[sb+1] = s1; s_sum[sb+2] = s2; s_sum[sb+3] = s3;
    s_sq [sb] = q0; s_sq [sb+1] = q1; s_sq [sb+2] = q2; s_sq [sb+3] = q3;
    s_mn [sb] = m0; s_mn [sb+1] = m1; s_mn [sb+2] = m2; s_mn [sb+3] = m3;
    s_mx [sb] = M0; s_mx [sb+1] = M1; s_mx [sb+2] = M2; s_mx [sb+3] = M3;
    __syncthreads();

    float sum = s_sum[t] + s_sum[t+128] + s_sum[t+256] + s_sum[t+384];
    float sq  = s_sq [t] + s_sq [t+128] + s_sq [t+256] + s_sq [t+384];
    float mn  = fminf(fminf(s_mn[t], s_mn[t+128]), fminf(s_mn[t+256], s_mn[t+384]));
    float mx  = fmaxf(fmaxf(s_mx[t], s_mx[t+128]), fmaxf(s_mx[t+256], s_mx[t+384]));

    float fc   = fmaxf((float)cnt, 1.0f);
    float mean = sum / fc;
    float stdv = sqrtf(fmaxf(sq / fc - mean * mean, 1e-9f));
    if (cnt == 0) { mn = 0.f; mx = 0.f; }

    size_t fb = (size_t)g * KTOT + t;
    g_fh[fb + 0 * D] = __float2half_rn(sum * 0.14142135623730951f);  // 1/sqrt(50)
    g_fh[fb + 1 * D] = __float2half_rn(mean);
    g_fh[fb + 2 * D] = __float2half_rn(mn);
    g_fh[fb + 3 * D] = __float2half_rn(mx);
    g_fh[fb + 4 * D] = __float2half_rn(stdv);
}

// ---------------------------------------------------------------------------
// Kernel 3: GEMM out += feats[G,640] @ W (split-K=2, atomic accumulate).
// fp16 2-pass (A*Bhi + A*Blo). BM=64, BN=64, BK=64; 256 threads; warp 32x16.
// cp.async double buffer; ldmatrix.x4 fragments. grid = (G/64)*2*2 = 628;
// occupancy 4 blocks/SM (4 x 55.3KB = 221KB < 228KB).
// ---------------------------------------------------------------------------
#define SSTR    72
#define T_BUF   (64 * SSTR)                 // 4608 halfs
#define STAGE   (3 * T_BUF)                 // 13824 halfs
#define SMEM_ELEMS (2 * STAGE)              // 55296 B
#define NKT     (KTOT / 64)                 // 10
#define KHALF   (NKT / 2)                   // 5

__device__ __forceinline__ void cp16(__half* dst, const __half* src)
{
    unsigned sa = (unsigned)__cvta_generic_to_shared(dst);
    asm volatile("cp.async.cg.shared.global [%0], [%1], 16;\n" :: "r"(sa), "l"(src));
}

#define LDSM4(r0, r1, r2, r3, addr)                                           \
    asm volatile("ldmatrix.sync.aligned.m8n8.x4.shared.b16 {%0,%1,%2,%3}, [%4];" \
        : "=r"(r0), "=r"(r1), "=r"(r2), "=r"(r3) : "r"(addr))

#define MMA_F16(acc, a0, a1, a2, a3, b0, b1)                                  \
    asm volatile(                                                             \
        "mma.sync.aligned.m16n8k16.row.col.f32.f16.f16.f32 "                  \
        "{%0,%1,%2,%3}, {%4,%5,%6,%7}, {%8,%9}, {%0,%1,%2,%3};\n"             \
        : "+f"((acc)[0]), "+f"((acc)[1]), "+f"((acc)[2]), "+f"((acc)[3])      \
        : "r"(a0), "r"(a1), "r"(a2), "r"(a3), "r"(b0), "r"(b1))

__global__ __launch_bounds__(256, 4) void gemm_kernel(float* __restrict__ out, int G)
{
    extern __shared__ __half sm[];
    int tid  = threadIdx.x;
    int warp = tid >> 5;
    int lane = tid & 31;
    int wm   = warp >> 2;
    int wn   = warp & 3;
    int bx   = blockIdx.x;
    int bm   = (bx >> 2) * 64;
    int bn   = ((bx >> 1) & 1) * 64;
    int kt0  = (bx & 1) * KHALF;

    float acc[2][2][4];
    #pragma unroll
    for (int mt = 0; mt < 2; ++mt)
        #pragma unroll
        for (int nt = 0; nt < 2; ++nt)
            #pragma unroll
            for (int r2 = 0; r2 < 4; ++r2) acc[mt][nt][r2] = 0.f;

    unsigned smbase = (unsigned)__cvta_generic_to_shared(sm);
    int mat = lane >> 3, rr = lane & 7;
    unsigned offA0 = ((wm * 32 +      (mat & 1) * 8 + rr) * SSTR + (mat >> 1) * 8) * 2;
    unsigned offA1 = ((wm * 32 + 16 + (mat & 1) * 8 + rr) * SSTR + (mat >> 1) * 8) * 2;
    unsigned offB  = ((unsigned)T_BUF + (wn * 16 + (mat >> 1) * 8 + rr) * SSTR
                      + (mat & 1) * 8) * 2;

    auto load_stage = [&](int s, int kt) {
        int kb = kt * 64;
        #pragma unroll
        for (int i = 0; i < 6; ++i) {
            int c   = tid + i * 256;
            int buf = c >> 9;                  // 0:A 1:Bhi 2:Blo
            int c2  = c & 511;
            int row = c2 >> 3;
            int cw  = c2 & 7;
            const __half* src;
            if (buf == 0)      src = g_fh + (size_t)(bm + row) * KTOT + kb + cw * 8;
            else if (buf == 1) src = g_wh + (size_t)(bn + row) * KTOT + kb + cw * 8;
            else               src = g_wl + (size_t)(bn + row) * KTOT + kb + cw * 8;
            cp16(sm + s * STAGE + buf * T_BUF + row * SSTR + cw * 8, src);
        }
    };

    load_stage(0, kt0);
    asm volatile("cp.async.commit_group;\n");

    for (int kt = kt0; kt < kt0 + KHALF; ++kt) {
        int s = (kt - kt0) & 1;
        if (kt + 1 < kt0 + KHALF) {
            load_stage(s ^ 1, kt + 1);
            asm volatile("cp.async.commit_group;\n");
            asm volatile("cp.async.wait_group 1;\n");
        } else {
            asm volatile("cp.async.wait_group 0;\n");
        }
        __syncthreads();

        unsigned sOff = smbase + (unsigned)(s * STAGE) * 2;

        #pragma unroll
        for (int ks = 0; ks < 4; ++ks) {
            unsigned kOff = (unsigned)(ks * 16) * 2;
            unsigned a0[4], a1[4], bh[4], bl[4];
            LDSM4(a0[0], a0[1], a0[2], a0[3], sOff + offA0 + kOff);
            LDSM4(a1[0], a1[1], a1[2], a1[3], sOff + offA1 + kOff);
            LDSM4(bh[0], bh[1], bh[2], bh[3], sOff + offB + kOff);
            LDSM4(bl[0], bl[1], bl[2], bl[3], sOff + offB + (unsigned)(T_BUF * 2) + kOff);

            MMA_F16(acc[0][0], a0[0], a0[1], a0[2], a0[3], bh[0], bh[1]);
            MMA_F16(acc[0][1], a0[0], a0[1], a0[2], a0[3], bh[2], bh[3]);
            MMA_F16(acc[1][0], a1[0], a1[1], a1[2], a1[3], bh[0], bh[1]);
            MMA_F16(acc[1][1], a1[0], a1[1], a1[2], a1[3], bh[2], bh[3]);
            MMA_F16(acc[0][0], a0[0], a0[1], a0[2], a0[3], bl[0], bl[1]);
            MMA_F16(acc[0][1], a0[0], a0[1], a0[2], a0[3], bl[2], bl[3]);
            MMA_F16(acc[1][0], a1[0], a1[1], a1[2], a1[3], bl[0], bl[1]);
            MMA_F16(acc[1][1], a1[0], a1[1], a1[2], a1[3], bl[2], bl[3]);
        }
        __syncthreads();
    }

    // Epilogue: atomic accumulate into out (bias pre-initialized)
    #pragma unroll
    for (int mt = 0; mt < 2; ++mt) {
        #pragma unroll
        for (int nt = 0; nt < 2; ++nt) {
            int row = bm + wm * 32 + mt * 16 + (lane >> 2);
            int n   = bn + wn * 16 + nt * 8 + (lane & 3) * 2;
            if (row < G) {
                atomicAdd(out + (size_t)row * 128 + n,     acc[mt][nt][0]);
                atomicAdd(out + (size_t)row * 128 + n + 1, acc[mt][nt][1]);
            }
            if (row + 8 < G) {
                atomicAdd(out + (size_t)(row + 8) * 128 + n,     acc[mt][nt][2]);
                atomicAdd(out + (size_t)(row + 8) * 128 + n + 1, acc[mt][nt][3]);
            }
        }
    }
}

// ---------------------------------------------------------------------------
// Launch. Inputs: x[f32 N*128], batch[int64/int32 N], W[f32 640*128],
// b[f32 128], num_segments (ignored; G = out_size/128).
// ---------------------------------------------------------------------------
extern "C" void kernel_launch(void* const* d_in, const int* in_sizes, int n_in,
                              void* d_out, int out_size)
{
    const float* x     = (const float*)d_in[0];
    const int*   batch = (const int*)d_in[1];
    const float* W     = (const float*)d_in[2];
    const float* bias  = (const float*)d_in[3];
    float*       out   = (float*)d_out;

    int N = in_sizes[0] / D;
    int G = out_size / 128;
    int NB = (N + 511) / 512;
    int total4 = (G * 128) / 4;
    int IB = (total4 + 255) / 256;

    static bool attr_done = false;
    if (!attr_done) {
        cudaFuncSetAttribute(gemm_kernel,
                             cudaFuncAttributeMaxDynamicSharedMemorySize,
                             SMEM_ELEMS * (int)sizeof(__half));
        attr_done = true;
    }

    scan_kernel<<<NB + IB, 256>>>(batch, bias, out, N, G, NB, total4);
    seg_reduce_kernel<<<G + WTILES, 128>>>(x, W, G);
    gemm_kernel<<<((G + 63) / 64) * 4, 256, SMEM_ELEMS * sizeof(__half)>>>(out, G);
}

// round 15
// speedup vs baseline: 1.1083x; 1.0065x over previous
#include <cuda_runtime.h>
#include <cuda_fp16.h>
#include <cstdint>

#define D       128
#define KTOT    640
#define MAXG    10048        // padded segment capacity (multiple of 64)
#define WTILES  80           // 20 k-tiles x 4 n-tiles of 32x32 for W split

// Scratch (device globals; zero-initialized; feats rows >= G stay 0 forever)
__device__ int g_segoff[MAXG + 1];
__device__ __align__(16) __half g_fh[(size_t)MAXG * KTOT];   // feats fp16
// W TRANSPOSED [n=128][k=640], fp16 hi/lo split
__device__ __align__(16) __half g_wh[128 * KTOT];
__device__ __align__(16) __half g_wl[128 * KTOT];

// ---------------------------------------------------------------------------
// Kernel 1 (scan + bias-init fused launch):
//  blocks [0,NB): boundary scan over sorted batch -> segment offsets,
//    2 ids/thread; dtype probed ONCE per block (smem broadcast — avoids
//    570k same-address LDGs hammering one LTS partition).
//  blocks [NB,...): initialize out with bias (gemm accumulates atomically).
// ---------------------------------------------------------------------------
__global__ __launch_bounds__(256) void scan_kernel(const int* __restrict__ words,
                                                   const float* __restrict__ bias,
                                                   float* __restrict__ out,
                                                   int N, int G, int NB, int total4)
{
    int b = blockIdx.x;
    int t = threadIdx.x;

    if (b >= NB) {
        int j = (b - NB) * 256 + t;
        if (j < total4) {
            int n = (j * 4) & 127;
            float4 v = { __ldg(bias + n), __ldg(bias + n + 1),
                         __ldg(bias + n + 2), __ldg(bias + n + 3) };
            *(float4*)(out + (size_t)j * 4) = v;
        }
        return;
    }

    __shared__ int s_is64;
    if (t == 0) s_is64 = (words[N - 1] == 0);   // int64 -> high word of last id = 0
    __syncthreads();
    const bool is64 = s_is64;

    int i0 = (b * 256 + t) * 2;
    if (i0 >= N) return;

    if (i0 + 3 <= N) {
        int v0, v1, v2;
        if (is64) {
            int4 w = *(const int4*)(words + 2 * i0);
            v0 = w.x; v1 = w.z;
            v2 = words[2 * (i0 + 2)];
        } else {
            int2 w = *(const int2*)(words + i0);
            v0 = w.x; v1 = w.y;
            v2 = words[i0 + 2];
        }
        if (i0 == 0)
            for (int g = 0; g <= v0; ++g) g_segoff[g] = 0;
        for (int g = v0 + 1; g <= v1; ++g) g_segoff[g] = i0 + 1;
        for (int g = v1 + 1; g <= v2; ++g) g_segoff[g] = i0 + 2;
    } else {
        for (int i = i0; i < N && i < i0 + 2; ++i) {
            int bi = is64 ? words[2 * i] : words[i];
            if (i == 0)
                for (int g = 0; g <= bi; ++g) g_segoff[g] = 0;
            if (i == N - 1) {
                for (int g = bi + 1; g <= G; ++g) g_segoff[g] = N;
            } else {
                int bn = is64 ? words[2 * (i + 1)] : words[i + 1];
                for (int g = bi + 1; g <= bn; ++g) g_segoff[g] = i + 1;
            }
        }
    }
}

// ---------------------------------------------------------------------------
// Kernel 2 (fused): blocks [0,G): per-segment reduction (streams 256MB);
// blocks [G,G+WTILES): W split+transpose (hidden under the reduce).
// Packed arithmetic: sum/sumsq via f32x2, min/max via f16x2 (exact).
// feats row: [sum/sqrt(50) | mean | min | max | std] (5 x 128), fp16.
// ---------------------------------------------------------------------------
#define ACCP(v)                                                                \
    do {                                                                       \
        uint64_t p01, p23; unsigned h01u, h23u;                                \
        asm("mov.b64 %0,{%1,%2};" : "=l"(p01) : "f"((v).x), "f"((v).y));       \
        asm("mov.b64 %0,{%1,%2};" : "=l"(p23) : "f"((v).z), "f"((v).w));       \
        asm("add.rn.f32x2 %0,%0,%1;" : "+l"(sum01) : "l"(p01));                \
        asm("add.rn.f32x2 %0,%0,%1;" : "+l"(sum23) : "l"(p23));                \
        asm("fma.rn.f32x2 %0,%1,%1,%0;" : "+l"(sq01) : "l"(p01));              \
        asm("fma.rn.f32x2 %0,%1,%1,%0;" : "+l"(sq23) : "l"(p23));              \
        asm("cvt.rn.f16x2.f32 %0,%1,%2;" : "=r"(h01u) : "f"((v).y), "f"((v).x)); \
        asm("cvt.rn.f16x2.f32 %0,%1,%2;" : "=r"(h23u) : "f"((v).w), "f"((v).z)); \
        __half2 hh01 = *reinterpret_cast<__half2*>(&h01u);                     \
        __half2 hh23 = *reinterpret_cast<__half2*>(&h23u);                     \
        mn01 = __hmin2(mn01, hh01); mx01 = __hmax2(mx01, hh01);                \
        mn23 = __hmin2(mn23, hh23); mx23 = __hmax2(mx23, hh23);                \
    } while (0)

__global__ __launch_bounds__(128) void seg_reduce_kernel(const float* __restrict__ x,
                                                         const float* __restrict__ W,
                                                         int G)
{
    int t = threadIdx.x;
    int gb = blockIdx.x;

    if (gb >= G) {
        // ---- W split + transpose: 32x32 tile, both sides coalesced ----
        __shared__ float s[32][33];
        int tb = gb - G;
        int k0 = (tb % 20) * 32;
        int n0 = (tb / 20) * 32;
        int tx = t & 31;
        int ty = t >> 5;                   // 0..3
        #pragma unroll
        for (int it = 0; it < 8; ++it) {
            int r = ty + it * 4;
            s[r][tx] = W[(size_t)(k0 + r) * 128 + n0 + tx];
        }
        __syncthreads();
        #pragma unroll
        for (int it = 0; it < 8; ++it) {
            int n = ty + it * 4;
            float v = s[tx][n];
            __half h = __float2half_rn(v);
            size_t o = (size_t)(n0 + n) * KTOT + k0 + tx;
            g_wh[o] = h;
            g_wl[o] = __float2half_rn(v - __half2float(h));
        }
        return;
    }

    int g = gb;
    int rg   = t >> 5;
    int lane = t & 31;
    int c4   = lane * 4;

    int s0v = g_segoff[g];
    int e0v = g_segoff[g + 1];
    int cnt = e0v - s0v;

    uint64_t sum01 = 0ULL, sum23 = 0ULL, sq01 = 0ULL, sq23 = 0ULL;
    const __half2 hpos = __halves2half2(__ushort_as_half(0x7C00), __ushort_as_half(0x7C00));
    const __half2 hneg = __halves2half2(__ushort_as_half(0xFC00), __ushort_as_half(0xFC00));
    __half2 mn01 = hpos, mn23 = hpos, mx01 = hneg, mx23 = hneg;

    const float* base = x + (size_t)s0v * D + c4;
    int r = rg;
    for (; r + 12 < cnt; r += 16) {        // 4 float4 in flight
        float4 v0 = __ldcs((const float4*)(base + (size_t)r * D));
        float4 v1 = __ldcs((const float4*)(base + (size_t)(r + 4) * D));
        float4 v2 = __ldcs((const float4*)(base + (size_t)(r + 8) * D));
        float4 v3 = __ldcs((const float4*)(base + (size_t)(r + 12) * D));
        ACCP(v0); ACCP(v1); ACCP(v2); ACCP(v3);
    }
    for (; r + 4 < cnt; r += 8) {
        float4 v0 = __ldcs((const float4*)(base + (size_t)r * D));
        float4 v1 = __ldcs((const float4*)(base + (size_t)(r + 4) * D));
        ACCP(v0); ACCP(v1);
    }
    for (; r < cnt; r += 4) {
        float4 v0 = __ldcs((const float4*)(base + (size_t)r * D));
        ACCP(v0);
    }

    float s0, s1, s2, s3, q0, q1, q2, q3;
    asm("mov.b64 {%0,%1},%2;" : "=f"(s0), "=f"(s1) : "l"(sum01));
    asm("mov.b64 {%0,%1},%2;" : "=f"(s2), "=f"(s3) : "l"(sum23));
    asm("mov.b64 {%0,%1},%2;" : "=f"(q0), "=f"(q1) : "l"(sq01));
    asm("mov.b64 {%0,%1},%2;" : "=f"(q2), "=f"(q3) : "l"(sq23));
    float m0 = __low2float(mn01), m1 = __high2float(mn01);
    float m2 = __low2float(mn23), m3 = __high2float(mn23);
    float M0 = __low2float(mx01), M1 = __high2float(mx01);
    float M2 = __low2float(mx23), M3 = __high2float(mx23);

    __shared__ float s_sum[512], s_sq[512], s_mn[512], s_mx[512];
    int sb = rg * 128 + c4;
    s_sum[sb] = s0; s_sum[sb+1] = s1; s_sum[sb+2] = s2; s_sum[sb+3] = s3;
    s_sq [sb] = q0; s_sq [sb+1] = q1; s_sq [sb+2] = q2; s_sq [sb+3] = q3;
    s_mn [sb] = m0; s_mn [sb+1] = m1; s_mn [sb+2] = m2; s_mn [sb+3] = m3;
    s_mx [sb] = M0; s_mx [sb+1] = M1; s_mx [sb+2] = M2; s_mx [sb+3] = M3;
    __syncthreads();

    float sum = s_sum[t] + s_sum[t+128] + s_sum[t+256] + s_sum[t+384];
    float sq  = s_sq [t] + s_sq [t+128] + s_sq [t+256] + s_sq [t+384];
    float mn  = fminf(fminf(s_mn[t], s_mn[t+128]), fminf(s_mn[t+256], s_mn[t+384]));
    float mx  = fmaxf(fmaxf(s_mx[t], s_mx[t+128]), fmaxf(s_mx[t+256], s_mx[t+384]));

    float fc   = fmaxf((float)cnt, 1.0f);
    float mean = sum / fc;
    float stdv = sqrtf(fmaxf(sq / fc - mean * mean, 1e-9f));
    if (cnt == 0) { mn = 0.f; mx = 0.f; }

    size_t fb = (size_t)g * KTOT + t;
    g_fh[fb + 0 * D] = __float2half_rn(sum * 0.14142135623730951f);  // 1/sqrt(50)
    g_fh[fb + 1 * D] = __float2half_rn(mean);
    g_fh[fb + 2 * D] = __float2half_rn(mn);
    g_fh[fb + 3 * D] = __float2half_rn(mx);
    g_fh[fb + 4 * D] = __float2half_rn(stdv);
}

// ---------------------------------------------------------------------------
// Kernel 3: GEMM out += feats[G,640] @ W (split-K=2, vectorized red.add).
// fp16 2-pass (A*Bhi + A*Blo). BM=64, BN=64, BK=64; 256 threads; warp 32x16.
// Single-sync 2-stage cp.async pipeline; ldmatrix.x4 fragments.
// grid = (G/64)*2*2 = 628; occupancy 4 blocks/SM.
// ---------------------------------------------------------------------------
#define SSTR    72
#define T_BUF   (64 * SSTR)                 // 4608 halfs
#define STAGE   (3 * T_BUF)                 // 13824 halfs
#define SMEM_ELEMS (2 * STAGE)              // 55296 B
#define NKT     (KTOT / 64)                 // 10
#define KHALF   (NKT / 2)                   // 5

__device__ __forceinline__ void cp16(__half* dst, const __half* src)
{
    unsigned sa = (unsigned)__cvta_generic_to_shared(dst);
    asm volatile("cp.async.cg.shared.global [%0], [%1], 16;\n" :: "r"(sa), "l"(src));
}

#define LDSM4(r0, r1, r2, r3, addr)                                           \
    asm volatile("ldmatrix.sync.aligned.m8n8.x4.shared.b16 {%0,%1,%2,%3}, [%4];" \
        : "=r"(r0), "=r"(r1), "=r"(r2), "=r"(r3) : "r"(addr))

#define MMA_F16(acc, a0, a1, a2, a3, b0, b1)                                  \
    asm volatile(                                                             \
        "mma.sync.aligned.m16n8k16.row.col.f32.f16.f16.f32 "                  \
        "{%0,%1,%2,%3}, {%4,%5,%6,%7}, {%8,%9}, {%0,%1,%2,%3};\n"             \
        : "+f"((acc)[0]), "+f"((acc)[1]), "+f"((acc)[2]), "+f"((acc)[3])      \
        : "r"(a0), "r"(a1), "r"(a2), "r"(a3), "r"(b0), "r"(b1))

#define REDV2(ptr, a, b)                                                      \
    asm volatile("red.global.add.v2.f32 [%0], {%1,%2};"                       \
        :: "l"(ptr), "f"(a), "f"(b) : "memory")

__global__ __launch_bounds__(256, 4) void gemm_kernel(float* __restrict__ out, int G)
{
    extern __shared__ __half sm[];
    int tid  = threadIdx.x;
    int warp = tid >> 5;
    int lane = tid & 31;
    int wm   = warp >> 2;
    int wn   = warp & 3;
    int bx   = blockIdx.x;
    int bm   = (bx >> 2) * 64;
    int bn   = ((bx >> 1) & 1) * 64;
    int kt0  = (bx & 1) * KHALF;

    float acc[2][2][4];
    #pragma unroll
    for (int mt = 0; mt < 2; ++mt)
        #pragma unroll
        for (int nt = 0; nt < 2; ++nt)
            #pragma unroll
            for (int r2 = 0; r2 < 4; ++r2) acc[mt][nt][r2] = 0.f;

    unsigned smbase = (unsigned)__cvta_generic_to_shared(sm);
    int mat = lane >> 3, rr = lane & 7;
    unsigned offA0 = ((wm * 32 +      (mat & 1) * 8 + rr) * SSTR + (mat >> 1) * 8) * 2;
    unsigned offA1 = ((wm * 32 + 16 + (mat & 1) * 8 + rr) * SSTR + (mat >> 1) * 8) * 2;
    unsigned offB  = ((unsigned)T_BUF + (wn * 16 + (mat >> 1) * 8 + rr) * SSTR
                      + (mat & 1) * 8) * 2;

    auto load_stage = [&](int s, int kt) {
        int kb = kt * 64;
        #pragma unroll
        for (int i = 0; i < 6; ++i) {
            int c   = tid + i * 256;
            int buf = c >> 9;                  // 0:A 1:Bhi 2:Blo
            int c2  = c & 511;
            int row = c2 >> 3;
            int cw  = c2 & 7;
            const __half* src;
            if (buf == 0)      src = g_fh + (size_t)(bm + row) * KTOT + kb + cw * 8;
            else if (buf == 1) src = g_wh + (size_t)(bn + row) * KTOT + kb + cw * 8;
            else               src = g_wl + (size_t)(bn + row) * KTOT + kb + cw * 8;
            cp16(sm + s * STAGE + buf * T_BUF + row * SSTR + cw * 8, src);
        }
    };

    load_stage(0, kt0);
    asm volatile("cp.async.commit_group;\n");

    // Single-sync pipeline: wait (stage ready) -> barrier (everyone done with
    // the OTHER stage from the previous iteration) -> issue next load -> compute.
    for (int kt = kt0; kt < kt0 + KHALF; ++kt) {
        int s = (kt - kt0) & 1;
        asm volatile("cp.async.wait_group 0;\n");
        __syncthreads();
        if (kt + 1 < kt0 + KHALF) {
            load_stage(s ^ 1, kt + 1);
            asm volatile("cp.async.commit_group;\n");
        }

        unsigned sOff = smbase + (unsigned)(s * STAGE) * 2;

        #pragma unroll
        for (int ks = 0; ks < 4; ++ks) {
            unsigned kOff = (unsigned)(ks * 16) * 2;
            unsigned a0[4], a1[4], bh[4], bl[4];
            LDSM4(a0[0], a0[1], a0[2], a0[3], sOff + offA0 + kOff);
            LDSM4(a1[0], a1[1], a1[2], a1[3], sOff + offA1 + kOff);
            LDSM4(bh[0], bh[1], bh[2], bh[3], sOff + offB + kOff);
            LDSM4(bl[0], bl[1], bl[2], bl[3], sOff + offB + (unsigned)(T_BUF * 2) + kOff);

            MMA_F16(acc[0][0], a0[0], a0[1], a0[2], a0[3], bh[0], bh[1]);
            MMA_F16(acc[0][1], a0[0], a0[1], a0[2], a0[3], bh[2], bh[3]);
            MMA_F16(acc[1][0], a1[0], a1[1], a1[2], a1[3], bh[0], bh[1]);
            MMA_F16(acc[1][1], a1[0], a1[1], a1[2], a1[3], bh[2], bh[3]);
            MMA_F16(acc[0][0], a0[0], a0[1], a0[2], a0[3], bl[0], bl[1]);
            MMA_F16(acc[0][1], a0[0], a0[1], a0[2], a0[3], bl[2], bl[3]);
            MMA_F16(acc[1][0], a1[0], a1[1], a1[2], a1[3], bl[0], bl[1]);
            MMA_F16(acc[1][1], a1[0], a1[1], a1[2], a1[3], bl[2], bl[3]);
        }
    }

    // Epilogue: vectorized reduction into out (bias pre-initialized)
    #pragma unroll
    for (int mt = 0; mt < 2; ++mt) {
        #pragma unroll
        for (int nt = 0; nt < 2; ++nt) {
            int row = bm + wm * 32 + mt * 16 + (lane >> 2);
            int n   = bn + wn * 16 + nt * 8 + (lane & 3) * 2;
            if (row < G)
                REDV2(out + (size_t)row * 128 + n, acc[mt][nt][0], acc[mt][nt][1]);
            if (row + 8 < G)
                REDV2(out + (size_t)(row + 8) * 128 + n, acc[mt][nt][2], acc[mt][nt][3]);
        }
    }
}

// ---------------------------------------------------------------------------
// Launch. Inputs: x[f32 N*128], batch[int64/int32 N], W[f32 640*128],
// b[f32 128], num_segments (ignored; G = out_size/128).
// ---------------------------------------------------------------------------
extern "C" void kernel_launch(void* const* d_in, const int* in_sizes, int n_in,
                              void* d_out, int out_size)
{
    const float* x     = (const float*)d_in[0];
    const int*   batch = (const int*)d_in[1];
    const float* W     = (const float*)d_in[2];
    const float* bias  = (const float*)d_in[3];
    float*       out   = (float*)d_out;

    int N = in_sizes[0] / D;
    int G = out_size / 128;
    int NB = (N + 511) / 512;
    int total4 = (G * 128) / 4;
    int IB = (total4 + 255) / 256;

    static bool attr_done = false;
    if (!attr_done) {
        cudaFuncSetAttribute(gemm_kernel,
                             cudaFuncAttributeMaxDynamicSharedMemorySize,
                             SMEM_ELEMS * (int)sizeof(__half));
        attr_done = true;
    }

    scan_kernel<<<NB + IB, 256>>>(batch, bias, out, N, G, NB, total4);
    seg_reduce_kernel<<<G + WTILES, 128>>>(x, W, G);
    gemm_kernel<<<((G + 63) / 64) * 4, 256, SMEM_ELEMS * sizeof(__half)>>>(out, G);
}

// round 16
// speedup vs baseline: 1.1370x; 1.0258x over previous
#include <cuda_runtime.h>
#include <cuda_fp16.h>
#include <cstdint>

#define D       128
#define KTOT    640
#define MAXG    10048        // padded segment capacity (multiple of 64)
#define WTILES  80           // 20 k-tiles x 4 n-tiles of 32x32 for W split

// Scratch (device globals; zero-initialized; feats rows >= G stay 0 forever)
__device__ int g_segoff[MAXG + 1];
__device__ __align__(16) __half g_fh[(size_t)MAXG * KTOT];   // feats fp16
// W TRANSPOSED [n=128][k=640], fp16 hi/lo split
__device__ __align__(16) __half g_wh[128 * KTOT];
__device__ __align__(16) __half g_wl[128 * KTOT];

// ---------------------------------------------------------------------------
// Kernel 1 (scan + bias-init fused launch):
//  blocks [0,NB): boundary scan over sorted batch -> segment offsets.
//  blocks [NB,...): initialize out with bias (gemm accumulates atomically).
// Triggers PDL completion early so the reduce grid ramps underneath.
// ---------------------------------------------------------------------------
__global__ __launch_bounds__(256) void scan_kernel(const int* __restrict__ words,
                                                   const float* __restrict__ bias,
                                                   float* __restrict__ out,
                                                   int N, int G, int NB, int total4)
{
    cudaTriggerProgrammaticLaunchCompletion();
    int b = blockIdx.x;
    int t = threadIdx.x;

    if (b >= NB) {
        int j = (b - NB) * 256 + t;
        if (j < total4) {
            int n = (j * 4) & 127;
            float4 v = { __ldg(bias + n), __ldg(bias + n + 1),
                         __ldg(bias + n + 2), __ldg(bias + n + 3) };
            *(float4*)(out + (size_t)j * 4) = v;
        }
        return;
    }

    __shared__ int s_is64;
    if (t == 0) s_is64 = (words[N - 1] == 0);   // int64 -> high word of last id = 0
    __syncthreads();
    const bool is64 = s_is64;

    int i0 = (b * 256 + t) * 2;
    if (i0 >= N) return;

    if (i0 + 3 <= N) {
        int v0, v1, v2;
        if (is64) {
            int4 w = *(const int4*)(words + 2 * i0);
            v0 = w.x; v1 = w.z;
            v2 = words[2 * (i0 + 2)];
        } else {
            int2 w = *(const int2*)(words + i0);
            v0 = w.x; v1 = w.y;
            v2 = words[i0 + 2];
        }
        if (i0 == 0)
            for (int g = 0; g <= v0; ++g) g_segoff[g] = 0;
        for (int g = v0 + 1; g <= v1; ++g) g_segoff[g] = i0 + 1;
        for (int g = v1 + 1; g <= v2; ++g) g_segoff[g] = i0 + 2;
    } else {
        for (int i = i0; i < N && i < i0 + 2; ++i) {
            int bi = is64 ? words[2 * i] : words[i];
            if (i == 0)
                for (int g = 0; g <= bi; ++g) g_segoff[g] = 0;
            if (i == N - 1) {
                for (int g = bi + 1; g <= G; ++g) g_segoff[g] = N;
            } else {
                int bn = is64 ? words[2 * (i + 1)] : words[i + 1];
                for (int g = bi + 1; g <= bn; ++g) g_segoff[g] = i + 1;
            }
        }
    }
}

// ---------------------------------------------------------------------------
// Kernel 2 (fused): blocks [0,G): per-segment reduction (streams 256MB);
// blocks [G,G+WTILES): W split+transpose (no dependency on scan -> runs
// fully overlapped with it under PDL).
// Packed arithmetic: sum/sumsq via f32x2, min/max via f16x2 (exact).
// feats row: [sum/sqrt(50) | mean | min | max | std] (5 x 128), fp16.
// ---------------------------------------------------------------------------
#define ACCP(v)                                                                \
    do {                                                                       \
        uint64_t p01, p23; unsigned h01u, h23u;                                \
        asm("mov.b64 %0,{%1,%2};" : "=l"(p01) : "f"((v).x), "f"((v).y));       \
        asm("mov.b64 %0,{%1,%2};" : "=l"(p23) : "f"((v).z), "f"((v).w));       \
        asm("add.rn.f32x2 %0,%0,%1;" : "+l"(sum01) : "l"(p01));                \
        asm("add.rn.f32x2 %0,%0,%1;" : "+l"(sum23) : "l"(p23));                \
        asm("fma.rn.f32x2 %0,%1,%1,%0;" : "+l"(sq01) : "l"(p01));              \
        asm("fma.rn.f32x2 %0,%1,%1,%0;" : "+l"(sq23) : "l"(p23));              \
        asm("cvt.rn.f16x2.f32 %0,%1,%2;" : "=r"(h01u) : "f"((v).y), "f"((v).x)); \
        asm("cvt.rn.f16x2.f32 %0,%1,%2;" : "=r"(h23u) : "f"((v).w), "f"((v).z)); \
        __half2 hh01 = *reinterpret_cast<__half2*>(&h01u);                     \
        __half2 hh23 = *reinterpret_cast<__half2*>(&h23u);                     \
        mn01 = __hmin2(mn01, hh01); mx01 = __hmax2(mx01, hh01);                \
        mn23 = __hmin2(mn23, hh23); mx23 = __hmax2(mx23, hh23);                \
    } while (0)

__global__ __launch_bounds__(128) void seg_reduce_kernel(const float* __restrict__ x,
                                                         const float* __restrict__ W,
                                                         int G)
{
    cudaTriggerProgrammaticLaunchCompletion();
    int t = threadIdx.x;
    int gb = blockIdx.x;

    if (gb >= G) {
        // ---- W split + transpose: independent of scan, no grid sync ----
        __shared__ float s[32][33];
        int tb = gb - G;
        int k0 = (tb % 20) * 32;
        int n0 = (tb / 20) * 32;
        int tx = t & 31;
        int ty = t >> 5;                   // 0..3
        #pragma unroll
        for (int it = 0; it < 8; ++it) {
            int r = ty + it * 4;
            s[r][tx] = W[(size_t)(k0 + r) * 128 + n0 + tx];
        }
        __syncthreads();
        #pragma unroll
        for (int it = 0; it < 8; ++it) {
            int n = ty + it * 4;
            float v = s[tx][n];
            __half h = __float2half_rn(v);
            size_t o = (size_t)(n0 + n) * KTOT + k0 + tx;
            g_wh[o] = h;
            g_wl[o] = __float2half_rn(v - __half2float(h));
        }
        return;
    }

    cudaGridDependencySynchronize();       // need g_segoff from scan

    int g = gb;
    int rg   = t >> 5;
    int lane = t & 31;
    int c4   = lane * 4;

    int s0v = g_segoff[g];
    int e0v = g_segoff[g + 1];
    int cnt = e0v - s0v;

    uint64_t sum01 = 0ULL, sum23 = 0ULL, sq01 = 0ULL, sq23 = 0ULL;
    const __half2 hpos = __halves2half2(__ushort_as_half(0x7C00), __ushort_as_half(0x7C00));
    const __half2 hneg = __halves2half2(__ushort_as_half(0xFC00), __ushort_as_half(0xFC00));
    __half2 mn01 = hpos, mn23 = hpos, mx01 = hneg, mx23 = hneg;

    const float* base = x + (size_t)s0v * D + c4;
    int r = rg;
    for (; r + 12 < cnt; r += 16) {        // 4 float4 in flight
        float4 v0 = __ldcs((const float4*)(base + (size_t)r * D));
        float4 v1 = __ldcs((const float4*)(base + (size_t)(r + 4) * D));
        float4 v2 = __ldcs((const float4*)(base + (size_t)(r + 8) * D));
        float4 v3 = __ldcs((const float4*)(base + (size_t)(r + 12) * D));
        ACCP(v0); ACCP(v1); ACCP(v2); ACCP(v3);
    }
    for (; r + 4 < cnt; r += 8) {
        float4 v0 = __ldcs((const float4*)(base + (size_t)r * D));
        float4 v1 = __ldcs((const float4*)(base + (size_t)(r + 4) * D));
        ACCP(v0); ACCP(v1);
    }
    for (; r < cnt; r += 4) {
        float4 v0 = __ldcs((const float4*)(base + (size_t)r * D));
        ACCP(v0);
    }

    float s0, s1, s2, s3, q0, q1, q2, q3;
    asm("mov.b64 {%0,%1},%2;" : "=f"(s0), "=f"(s1) : "l"(sum01));
    asm("mov.b64 {%0,%1},%2;" : "=f"(s2), "=f"(s3) : "l"(sum23));
    asm("mov.b64 {%0,%1},%2;" : "=f"(q0), "=f"(q1) : "l"(sq01));
    asm("mov.b64 {%0,%1},%2;" : "=f"(q2), "=f"(q3) : "l"(sq23));
    float m0 = __low2float(mn01), m1 = __high2float(mn01);
    float m2 = __low2float(mn23), m3 = __high2float(mn23);
    float M0 = __low2float(mx01), M1 = __high2float(mx01);
    float M2 = __low2float(mx23), M3 = __high2float(mx23);

    __shared__ float s_sum[512], s_sq[512], s_mn[512], s_mx[512];
    int sb = rg * 128 + c4;
    s_sum[sb] = s0; s_sum[sb+1] = s1; s_sum[sb+2] = s2; s_sum[sb+3] = s3;
    s_sq [sb] = q0; s_sq [sb+1] = q1; s_sq [sb+2] = q2; s_sq [sb+3] = q3;
    s_mn [sb] = m0; s_mn [sb+1] = m1; s_mn [sb+2] = m2; s_mn [sb+3] = m3;
    s_mx [sb] = M0; s_mx [sb+1] = M1; s_mx [sb+2] = M2; s_mx [sb+3] = M3;
    __syncthreads();

    float sum = s_sum[t] + s_sum[t+128] + s_sum[t+256] + s_sum[t+384];
    float sq  = s_sq [t] + s_sq [t+128] + s_sq [t+256] + s_sq [t+384];
    float mn  = fminf(fminf(s_mn[t], s_mn[t+128]), fminf(s_mn[t+256], s_mn[t+384]));
    float mx  = fmaxf(fmaxf(s_mx[t], s_mx[t+128]), fmaxf(s_mx[t+256], s_mx[t+384]));

    float fc   = fmaxf((float)cnt, 1.0f);
    float mean = sum / fc;
    float stdv = sqrtf(fmaxf(sq / fc - mean * mean, 1e-9f));
    if (cnt == 0) { mn = 0.f; mx = 0.f; }

    size_t fb = (size_t)g * KTOT + t;
    g_fh[fb + 0 * D] = __float2half_rn(sum * 0.14142135623730951f);  // 1/sqrt(50)
    g_fh[fb + 1 * D] = __float2half_rn(mean);
    g_fh[fb + 2 * D] = __float2half_rn(mn);
    g_fh[fb + 3 * D] = __float2half_rn(mx);
    g_fh[fb + 4 * D] = __float2half_rn(stdv);
}

// ---------------------------------------------------------------------------
// Kernel 3: GEMM out += feats[G,640] @ W (split-K=2, vectorized red.add).
// fp16 2-pass (A*Bhi + A*Blo). BM=64, BN=64, BK=64; 256 threads; warp 32x16.
// Single-sync 2-stage cp.async pipeline; ldmatrix.x4 fragments.
// grid = (G/64)*2*2 = 628; occupancy 4 blocks/SM. PDL: ramps under reduce.
// ---------------------------------------------------------------------------
#define SSTR    72
#define T_BUF   (64 * SSTR)                 // 4608 halfs
#define STAGE   (3 * T_BUF)                 // 13824 halfs
#define SMEM_ELEMS (2 * STAGE)              // 55296 B
#define NKT     (KTOT / 64)                 // 10
#define KHALF   (NKT / 2)                   // 5

__device__ __forceinline__ void cp16(__half* dst, const __half* src)
{
    unsigned sa = (unsigned)__cvta_generic_to_shared(dst);
    asm volatile("cp.async.cg.shared.global [%0], [%1], 16;\n" :: "r"(sa), "l"(src));
}

#define LDSM4(r0, r1, r2, r3, addr)                                           \
    asm volatile("ldmatrix.sync.aligned.m8n8.x4.shared.b16 {%0,%1,%2,%3}, [%4];" \
        : "=r"(r0), "=r"(r1), "=r"(r2), "=r"(r3) : "r"(addr))

#define MMA_F16(acc, a0, a1, a2, a3, b0, b1)                                  \
    asm volatile(                                                             \
        "mma.sync.aligned.m16n8k16.row.col.f32.f16.f16.f32 "                  \
        "{%0,%1,%2,%3}, {%4,%5,%6,%7}, {%8,%9}, {%0,%1,%2,%3};\n"             \
        : "+f"((acc)[0]), "+f"((acc)[1]), "+f"((acc)[2]), "+f"((acc)[3])      \
        : "r"(a0), "r"(a1), "r"(a2), "r"(a3), "r"(b0), "r"(b1))

#define REDV2(ptr, a, b)                                                      \
    asm volatile("red.global.add.v2.f32 [%0], {%1,%2};"                       \
        :: "l"(ptr), "f"(a), "f"(b) : "memory")

__global__ __launch_bounds__(256, 4) void gemm_kernel(float* __restrict__ out, int G)
{
    extern __shared__ __half sm[];
    int tid  = threadIdx.x;
    int warp = tid >> 5;
    int lane = tid & 31;
    int wm   = warp >> 2;
    int wn   = warp & 3;
    int bx   = blockIdx.x;
    int bm   = (bx >> 2) * 64;
    int bn   = ((bx >> 1) & 1) * 64;
    int kt0  = (bx & 1) * KHALF;

    float acc[2][2][4];
    #pragma unroll
    for (int mt = 0; mt < 2; ++mt)
        #pragma unroll
        for (int nt = 0; nt < 2; ++nt)
            #pragma unroll
            for (int r2 = 0; r2 < 4; ++r2) acc[mt][nt][r2] = 0.f;

    unsigned smbase = (unsigned)__cvta_generic_to_shared(sm);
    int mat = lane >> 3, rr = lane & 7;
    unsigned offA0 = ((wm * 32 +      (mat & 1) * 8 + rr) * SSTR + (mat >> 1) * 8) * 2;
    unsigned offA1 = ((wm * 32 + 16 + (mat & 1) * 8 + rr) * SSTR + (mat >> 1) * 8) * 2;
    unsigned offB  = ((unsigned)T_BUF + (wn * 16 + (mat >> 1) * 8 + rr) * SSTR
                      + (mat & 1) * 8) * 2;

    auto load_stage = [&](int s, int kt) {
        int kb = kt * 64;
        #pragma unroll
        for (int i = 0; i < 6; ++i) {
            int c   = tid + i * 256;
            int buf = c >> 9;                  // 0:A 1:Bhi 2:Blo
            int c2  = c & 511;
            int row = c2 >> 3;
            int cw  = c2 & 7;
            const __half* src;
            if (buf == 0)      src = g_fh + (size_t)(bm + row) * KTOT + kb + cw * 8;
            else if (buf == 1) src = g_wh + (size_t)(bn + row) * KTOT + kb + cw * 8;
            else               src = g_wl + (size_t)(bn + row) * KTOT + kb + cw * 8;
            cp16(sm + s * STAGE + buf * T_BUF + row * SSTR + cw * 8, src);
        }
    };

    cudaGridDependencySynchronize();       // need feats + bias-initialized out

    load_stage(0, kt0);
    asm volatile("cp.async.commit_group;\n");

    for (int kt = kt0; kt < kt0 + KHALF; ++kt) {
        int s = (kt - kt0) & 1;
        asm volatile("cp.async.wait_group 0;\n");
        __syncthreads();
        if (kt + 1 < kt0 + KHALF) {
            load_stage(s ^ 1, kt + 1);
            asm volatile("cp.async.commit_group;\n");
        }

        unsigned sOff = smbase + (unsigned)(s * STAGE) * 2;

        #pragma unroll
        for (int ks = 0; ks < 4; ++ks) {
            unsigned kOff = (unsigned)(ks * 16) * 2;
            unsigned a0[4], a1[4], bh[4], bl[4];
            LDSM4(a0[0], a0[1], a0[2], a0[3], sOff + offA0 + kOff);
            LDSM4(a1[0], a1[1], a1[2], a1[3], sOff + offA1 + kOff);
            LDSM4(bh[0], bh[1], bh[2], bh[3], sOff + offB + kOff);
            LDSM4(bl[0], bl[1], bl[2], bl[3], sOff + offB + (unsigned)(T_BUF * 2) + kOff);

            MMA_F16(acc[0][0], a0[0], a0[1], a0[2], a0[3], bh[0], bh[1]);
            MMA_F16(acc[0][1], a0[0], a0[1], a0[2], a0[3], bh[2], bh[3]);
            MMA_F16(acc[1][0], a1[0], a1[1], a1[2], a1[3], bh[0], bh[1]);
            MMA_F16(acc[1][1], a1[0], a1[1], a1[2], a1[3], bh[2], bh[3]);
            MMA_F16(acc[0][0], a0[0], a0[1], a0[2], a0[3], bl[0], bl[1]);
            MMA_F16(acc[0][1], a0[0], a0[1], a0[2], a0[3], bl[2], bl[3]);
            MMA_F16(acc[1][0], a1[0], a1[1], a1[2], a1[3], bl[0], bl[1]);
            MMA_F16(acc[1][1], a1[0], a1[1], a1[2], a1[3], bl[2], bl[3]);
        }
    }

    // Epilogue: vectorized reduction into out (bias pre-initialized)
    #pragma unroll
    for (int mt = 0; mt < 2; ++mt) {
        #pragma unroll
        for (int nt = 0; nt < 2; ++nt) {
            int row = bm + wm * 32 + mt * 16 + (lane >> 2);
            int n   = bn + wn * 16 + nt * 8 + (lane & 3) * 2;
            if (row < G)
                REDV2(out + (size_t)row * 128 + n, acc[mt][nt][0], acc[mt][nt][1]);
            if (row + 8 < G)
                REDV2(out + (size_t)(row + 8) * 128 + n, acc[mt][nt][2], acc[mt][nt][3]);
        }
    }
}

// ---------------------------------------------------------------------------
// Launch. Inputs: x[f32 N*128], batch[int64/int32 N], W[f32 640*128],
// b[f32 128], num_segments (ignored; G = out_size/128).
// PDL: reduce + gemm launched with programmatic stream serialization so their
// ramps overlap the previous kernel's execution.
// ---------------------------------------------------------------------------
extern "C" void kernel_launch(void* const* d_in, const int* in_sizes, int n_in,
                              void* d_out, int out_size)
{
    const float* x     = (const float*)d_in[0];
    const int*   batch = (const int*)d_in[1];
    const float* W     = (const float*)d_in[2];
    const float* bias  = (const float*)d_in[3];
    float*       out   = (float*)d_out;

    int N = in_sizes[0] / D;
    int G = out_size / 128;
    int NB = (N + 511) / 512;
    int total4 = (G * 128) / 4;
    int IB = (total4 + 255) / 256;

    static bool attr_done = false;
    if (!attr_done) {
        cudaFuncSetAttribute(gemm_kernel,
                             cudaFuncAttributeMaxDynamicSharedMemorySize,
                             SMEM_ELEMS * (int)sizeof(__half));
        attr_done = true;
    }

    scan_kernel<<<NB + IB, 256>>>(batch, bias, out, N, G, NB, total4);

    cudaLaunchAttribute pdl[1];
    pdl[0].id = cudaLaunchAttributeProgrammaticStreamSerialization;
    pdl[0].val.programmaticStreamSerializationAllowed = 1;

    {
        cudaLaunchConfig_t cfg = {};
        cfg.gridDim  = dim3(G + WTILES, 1, 1);
        cfg.blockDim = dim3(128, 1, 1);
        cfg.dynamicSmemBytes = 0;
        cfg.stream = 0;
        cfg.attrs = pdl;
        cfg.numAttrs = 1;
        cudaLaunchKernelEx(&cfg, seg_reduce_kernel, x, W, G);
    }
    {
        cudaLaunchConfig_t cfg = {};
        cfg.gridDim  = dim3(((G + 63) / 64) * 4, 1, 1);
        cfg.blockDim = dim3(256, 1, 1);
        cfg.dynamicSmemBytes = SMEM_ELEMS * sizeof(__half);
        cfg.stream = 0;
        cfg.attrs = pdl;
        cfg.numAttrs = 1;
        cudaLaunchKernelEx(&cfg, gemm_kernel, out, G);
    }
}